// round 16
// baseline (speedup 1.0000x reference)
#include <cuda_runtime.h>
#include <cuda_fp16.h>
#include <cstdint>

// ---------------------------------------------------------------------------
// WindowedCrossAttention — R16 (R15 + gemm_out race fix)
//   GEMM: W tile smem-RESIDENT (no per-chunk B traffic), 2-buffer A ring, KC=64.
//   Q-GEMM + KV-GEMM merged into one launch.
//   R15 bug: gemm_out synced BEFORE cp.async.wait_group -> read other threads'
//   unfinished copies -> NaN. Fixed: wait -> sync -> mma -> sync (WAR cover).
// ---------------------------------------------------------------------------

__device__ __half g_Q [4096ull * 64ull * 256ull];
__device__ __half g_KV[4096ull * 64ull * 512ull];
__device__ __half g_O [4096ull * 64ull * 256ull];
__device__ float  g_bias[8 * 64 * 64];                // [h][q][k]
__device__ __half g_Wh[1024 * 256];                   // [n][k]: Wq@0, Wkv@256, Wp@768

// ---- helpers ----------------------------------------------------------------
__device__ __forceinline__ uint32_t smem_u32(const void* p) {
    uint32_t a;
    asm("{ .reg .u64 t; cvta.to.shared.u64 t, %1; cvt.u32.u64 %0, t; }" : "=r"(a) : "l"(p));
    return a;
}
__device__ __forceinline__ void mma16816f16(float* c, const uint32_t* a, const uint32_t* b) {
    asm volatile(
        "mma.sync.aligned.m16n8k16.row.col.f32.f16.f16.f32 "
        "{%0,%1,%2,%3}, {%4,%5,%6,%7}, {%8,%9}, {%0,%1,%2,%3};"
        : "+f"(c[0]), "+f"(c[1]), "+f"(c[2]), "+f"(c[3])
        : "r"(a[0]), "r"(a[1]), "r"(a[2]), "r"(a[3]), "r"(b[0]), "r"(b[1]));
}
__device__ __forceinline__ void ldm_x4(uint32_t* r, uint32_t addr) {
    asm volatile("ldmatrix.sync.aligned.m8n8.x4.shared.b16 {%0,%1,%2,%3}, [%4];"
                 : "=r"(r[0]), "=r"(r[1]), "=r"(r[2]), "=r"(r[3]) : "r"(addr));
}
__device__ __forceinline__ uint32_t h2pack(float a, float b) {
    __half2 h = __floats2half2_rn(a, b);
    return *reinterpret_cast<uint32_t*>(&h);
}
#define CP_ASYNC16(dst, src) \
    asm volatile("cp.async.cg.shared.global [%0], [%1], 16;" :: "r"(dst), "l"(src))
#define CP_COMMIT() asm volatile("cp.async.commit_group;")
#define CP_WAIT0()  asm volatile("cp.async.wait_group 0;")
#define CP_WAIT1()  asm volatile("cp.async.wait_group 1;")

// ---- relative-position bias: g_bias[h][q][k] = bt[rel(q,k)][h] ---------------
__global__ void bias_kernel(const float* __restrict__ bt) {
    int idx = blockIdx.x * 256 + threadIdx.x;
    if (idx >= 8 * 64 * 64) return;
    int h  = idx >> 12;
    int nm = idx & 4095;
    int q = nm >> 6, k = nm & 63;
    int dy = (q >> 3) - (k >> 3);
    int dx = (q & 7) - (k & 7);
    int r  = (dy + 7) * 15 + (dx + 7);
    g_bias[idx] = bt[r * 8 + h];
}

// ---- fused W transpose: Wq/Wkv/Wp -> g_Wh[1024][256] fp16 --------------------
__global__ void convw_all(const float* __restrict__ Wq,
                          const float* __restrict__ Wkv,
                          const float* __restrict__ Wp) {
    int idx = blockIdx.x * 256 + threadIdx.x;
    if (idx >= 1024 * 256) return;
    int n = idx >> 8;
    int k = idx & 255;
    float v;
    if (n < 256)       v = Wq [k * 256 + n];
    else if (n < 768)  v = Wkv[k * 512 + (n - 256)];
    else               v = Wp [k * 256 + (n - 768)];
    g_Wh[idx] = __float2half_rn(v);
}

// ---- shared GEMM machinery ----------------------------------------------------
// smem: sBias@0 (512B), B resident @1024 (128 rows x 528B = 67584B),
//       A bufs @68608 + buf*18432 (128 rows x 144B)
#define SM_B     1024
#define SM_A     68608
#define GSM_TOTAL (68608 + 2 * 18432)

struct GemmCtx {
    uint32_t sb, aOff, bOff;
    int wm, wn, g, tig, tid;
};

__device__ __forceinline__ void gemm_init(GemmCtx& c, uint32_t sb) {
    c.sb = sb;
    c.tid = threadIdx.x;
    int wid = c.tid >> 5, lane = c.tid & 31;
    c.g = lane >> 2; c.tig = lane & 3;
    c.wm = wid & 1; c.wn = wid >> 1;
    uint32_t lrow = lane & 15, lcol = (lane >> 4) * 8;
    c.aOff = SM_A + (c.wm * 64 + lrow) * 144 + lcol * 2;
    c.bOff = SM_B + (c.wn * 32 + lrow) * 528 + lcol * 2;
}

__device__ __forceinline__ void gemm_loadB(const GemmCtx& c, int woff, int n0) {
#pragma unroll
    for (int i = 0; i < 16; ++i) {
        int idx = c.tid + i * 256;            // 0..4095: 128 rows x 32 segs
        int row = idx >> 5, seg = idx & 31;
        const __half* src = g_Wh + (long long)(woff + n0 + row) * 256 + seg * 8;
        CP_ASYNC16(c.sb + SM_B + row * 528 + seg * 16, src);
    }
}

__device__ __forceinline__ void gemm_mma(const GemmCtx& c, int buf, int kc,
                                         float acc[4][4][4]) {
    const uint32_t abase = c.sb + c.aOff + buf * 18432;
    const uint32_t bbase = c.sb + c.bOff + kc * 128;
#pragma unroll
    for (int ks = 0; ks < 4; ++ks) {
        uint32_t af[4][4], bm[2][4];
#pragma unroll
        for (int mf = 0; mf < 4; ++mf)
            ldm_x4(af[mf], abase + mf * 16 * 144 + ks * 32);
#pragma unroll
        for (int p = 0; p < 2; ++p)
            ldm_x4(bm[p], bbase + p * 16 * 528 + ks * 32);
#pragma unroll
        for (int mf = 0; mf < 4; ++mf)
#pragma unroll
            for (int p = 0; p < 2; ++p) {
                uint32_t b0[2] = {bm[p][0], bm[p][2]};
                uint32_t b1[2] = {bm[p][1], bm[p][3]};
                mma16816f16(acc[mf][2 * p + 0], af[mf], b0);
                mma16816f16(acc[mf][2 * p + 1], af[mf], b1);
            }
    }
}

// ---- merged Q + KV GEMM (A fp32 -> fp16 in loader) ----------------------------
__global__ __launch_bounds__(256, 2)
void gemm_qkv(const float* __restrict__ xq, const float* __restrict__ xs,
              const float* __restrict__ bq, const float* __restrict__ bkv,
              float qscale) {
    extern __shared__ __align__(1024) char smem[];
    const uint32_t sb = smem_u32(smem);
    GemmCtx c; gemm_init(c, sb);
    const int tid = c.tid;

    const bool isQ = (blockIdx.x < 2);
    const float* A     = isQ ? xq : xs;
    const float* bias  = isQ ? bq : bkv;
    const float scale  = isQ ? qscale : 1.f;
    const int   N      = isQ ? 256 : 512;
    const int   woff   = isQ ? 0 : 256;
    const int   n0     = (isQ ? blockIdx.x : blockIdx.x - 2) * 128;
    __half* C          = isQ ? g_Q : g_KV;
    const long long m0 = (long long)blockIdx.y * 128;

    float* sBias = (float*)smem;
    if (tid < 128) sBias[tid] = bias[n0 + tid];

    float acc[4][4][4];
#pragma unroll
    for (int i = 0; i < 4; ++i)
#pragma unroll
        for (int j = 0; j < 4; ++j)
#pragma unroll
            for (int q = 0; q < 4; ++q) acc[i][j][q] = 0.f;

    auto loadA = [&](int kc, float4* r) {
#pragma unroll
        for (int i = 0; i < 8; ++i) {
            int idx = tid + i * 256;
            int row = idx >> 4, q = idx & 15;
            r[i] = *reinterpret_cast<const float4*>(
                A + (m0 + row) * 256 + kc * 64 + q * 4);
        }
    };
    auto stsA = [&](int buf, const float4* r) {
        char* base = smem + SM_A + buf * 18432;
#pragma unroll
        for (int i = 0; i < 8; ++i) {
            int idx = tid + i * 256;
            int row = idx >> 4, q = idx & 15;
            float4 v = r[i];
            __half2 p0 = __floats2half2_rn(v.x, v.y);
            __half2 p1 = __floats2half2_rn(v.z, v.w);
            *reinterpret_cast<uint2*>(base + row * 144 + q * 8) =
                make_uint2(*reinterpret_cast<uint32_t*>(&p0),
                           *reinterpret_cast<uint32_t*>(&p1));
        }
    };

    // prologue: resident B (async) + A chunk 0 (sync LDG+STS)
    gemm_loadB(c, woff, n0);
    CP_COMMIT();
    {
        float4 r[8];
        loadA(0, r);
        stsA(0, r);
    }
    CP_WAIT0();                                    // own B copies done (pre-barrier)

    // main loop: 4 chunks, 2-buffer A ring, one sync per chunk
    // (sync at kc publishes: B for kc=0, and stsA(kc&1) from previous iter)
#pragma unroll 1
    for (int kc = 0; kc < 4; ++kc) {
        float4 r[8];
        if (kc < 3) loadA(kc + 1, r);              // LDG early
        __syncthreads();                           // prior reads of (kc+1)&1 done; STS visible
        if (kc < 3) stsA((kc + 1) & 1, r);
        gemm_mma(c, kc & 1, kc, acc);
    }

    // epilogue -> fp16 C
#pragma unroll
    for (int mf = 0; mf < 4; ++mf) {
#pragma unroll
        for (int nf = 0; nf < 4; ++nf) {
            const int cn = c.wn * 32 + nf * 8 + c.tig * 2;
            const float b0 = sBias[cn], b1 = sBias[cn + 1];
            const long long r0 = m0 + c.wm * 64 + mf * 16 + c.g;
            float v0 = scale * (acc[mf][nf][0] + b0);
            float v1 = scale * (acc[mf][nf][1] + b1);
            float v2 = scale * (acc[mf][nf][2] + b0);
            float v3 = scale * (acc[mf][nf][3] + b1);
            *reinterpret_cast<uint32_t*>(C + r0 * N + n0 + cn) = h2pack(v0, v1);
            *reinterpret_cast<uint32_t*>(C + (r0 + 8) * N + n0 + cn) = h2pack(v2, v3);
        }
    }
}

// ---- out-projection GEMM (A = g_O fp16 via cp.async) ---------------------------
// FIXED pipeline: cpA -> commit -> wait -> sync -> mma -> sync
__global__ __launch_bounds__(256, 2)
void gemm_out(const float* __restrict__ bias, float* __restrict__ Cp) {
    extern __shared__ __align__(1024) char smem[];
    const uint32_t sb = smem_u32(smem);
    GemmCtx c; gemm_init(c, sb);
    const int tid = c.tid;

    const int n0 = blockIdx.x * 128;
    const long long m0 = (long long)blockIdx.y * 128;

    float* sBias = (float*)smem;
    if (tid < 128) sBias[tid] = bias[n0 + tid];

    float acc[4][4][4];
#pragma unroll
    for (int i = 0; i < 4; ++i)
#pragma unroll
        for (int j = 0; j < 4; ++j)
#pragma unroll
            for (int q = 0; q < 4; ++q) acc[i][j][q] = 0.f;

    auto cpA = [&](int kc, int buf) {
        uint32_t base = sb + SM_A + buf * 18432;
#pragma unroll
        for (int i = 0; i < 4; ++i) {
            int idx = tid + i * 256;               // 1024 lines of 16B
            int row = idx >> 3, seg = idx & 7;
            const __half* src = g_O + (m0 + row) * 256 + kc * 64 + seg * 8;
            CP_ASYNC16(base + row * 144 + seg * 16, src);
        }
    };

    // prologue: resident B (G0) + A chunk 0 (G1)
    gemm_loadB(c, 768, n0);
    CP_COMMIT();
    cpA(0, 0);
    CP_COMMIT();

#pragma unroll 1
    for (int kc = 0; kc < 4; ++kc) {
        if (kc < 3) {
            cpA(kc + 1, (kc + 1) & 1);             // WAR vs mma(kc-1) covered by
            CP_COMMIT();                           // trailing sync of prev iter
        }
        if (kc < 3) CP_WAIT1(); else CP_WAIT0();   // own copies of chunk kc (+B) done
        __syncthreads();                           // publish ALL threads' copies
        gemm_mma(c, kc & 1, kc, acc);
        if (kc < 3) __syncthreads();               // reads done before next cpA overwrite
    }

#pragma unroll
    for (int mf = 0; mf < 4; ++mf) {
#pragma unroll
        for (int nf = 0; nf < 4; ++nf) {
            const int cn = c.wn * 32 + nf * 8 + c.tig * 2;
            const float b0 = sBias[cn], b1 = sBias[cn + 1];
            const long long r0 = m0 + c.wm * 64 + mf * 16 + c.g;
            float* p0 = Cp + r0 * 256 + n0 + cn;
            float* p1 = Cp + (r0 + 8) * 256 + n0 + cn;
            *reinterpret_cast<float2*>(p0) =
                make_float2(acc[mf][nf][0] + b0, acc[mf][nf][1] + b1);
            *reinterpret_cast<float2*>(p1) =
                make_float2(acc[mf][nf][2] + b0, acc[mf][nf][3] + b1);
        }
    }
}

// ---- attention via fp16 HMMA: block = 4 heads of 1 window (unchanged) ----------
#define ASM_TOTAL (20480 + 18432)

__global__ __launch_bounds__(256, 2)
void attn_mma() {
    extern __shared__ __align__(16) char smem[];
    __half* sK  = (__half*)smem;                 // [hl][key][40]
    __half* sVt = (__half*)(smem + 20480);       // [hl][d][72]

    const int w  = blockIdx.x;
    const int hg = blockIdx.y;
    const int tid = threadIdx.x;
    const __half* kvb = g_KV + (long long)w * 32768 + hg * 128;

#pragma unroll
    for (int i = 0; i < 4; ++i) {
        int idx = tid + i * 256;
        int hl  = idx >> 8;
        int rem = idx & 255;
        int key = rem >> 2;
        int d8  = (rem & 3) * 8;
        const __half* src = kvb + key * 512 + hl * 32 + d8;
        *reinterpret_cast<uint4*>(sK + hl * 2560 + key * 40 + d8) =
            *reinterpret_cast<const uint4*>(src);
        uint4 v4 = *reinterpret_cast<const uint4*>(src + 256);
        const __half* vh = reinterpret_cast<const __half*>(&v4);
        __half* vt = sVt + hl * 2304 + key;
#pragma unroll
        for (int j = 0; j < 8; ++j) vt[(d8 + j) * 72] = vh[j];
    }
    __syncthreads();

    const int wid = tid >> 5, lane = tid & 31;
    const int g = lane >> 2, t = lane & 3;
    const int hl = wid >> 1, mh = wid & 1;
    const int h  = hg * 4 + hl;
    const __half* Kh = sK + hl * 2560;
    const __half* Vh = sVt + hl * 2304;

    uint32_t qf[2][2][4];
    const __half* qbase = g_Q + (long long)w * 16384 + h * 32;
#pragma unroll
    for (int mt = 0; mt < 2; ++mt) {
        const int R = (mh * 2 + mt) * 16 + g;
#pragma unroll
        for (int kb = 0; kb < 2; ++kb) {
            const int cc = kb * 16 + t * 2;
            qf[mt][kb][0] = *reinterpret_cast<const uint32_t*>(qbase + R * 256 + cc);
            qf[mt][kb][1] = *reinterpret_cast<const uint32_t*>(qbase + (R + 8) * 256 + cc);
            qf[mt][kb][2] = *reinterpret_cast<const uint32_t*>(qbase + R * 256 + cc + 8);
            qf[mt][kb][3] = *reinterpret_cast<const uint32_t*>(qbase + (R + 8) * 256 + cc + 8);
        }
    }

    float S[2][8][4];
#pragma unroll
    for (int mt = 0; mt < 2; ++mt)
#pragma unroll
        for (int nb = 0; nb < 8; ++nb)
#pragma unroll
            for (int q = 0; q < 4; ++q) S[mt][nb][q] = 0.f;

#pragma unroll
    for (int nb = 0; nb < 8; ++nb) {
        uint32_t bf[2][2];
#pragma unroll
        for (int kb = 0; kb < 2; ++kb) {
            const __half* p = Kh + (8 * nb + g) * 40 + kb * 16 + t * 2;
            bf[kb][0] = *(const uint32_t*)p;
            bf[kb][1] = *(const uint32_t*)(p + 8);
        }
#pragma unroll
        for (int mt = 0; mt < 2; ++mt)
#pragma unroll
            for (int kb = 0; kb < 2; ++kb)
                mma16816f16(S[mt][nb], qf[mt][kb], bf[kb]);
    }

    const float* bb = g_bias + h * 4096;
#pragma unroll
    for (int mt = 0; mt < 2; ++mt) {
        const int R = (mh * 2 + mt) * 16 + g;
#pragma unroll
        for (int nb = 0; nb < 8; ++nb) {
            const int cc = nb * 8 + t * 2;
            float2 b0 = *reinterpret_cast<const float2*>(bb + R * 64 + cc);
            float2 b1 = *reinterpret_cast<const float2*>(bb + (R + 8) * 64 + cc);
            S[mt][nb][0] += b0.x; S[mt][nb][1] += b0.y;
            S[mt][nb][2] += b1.x; S[mt][nb][3] += b1.y;
        }
    }

    float inv[2][2];
#pragma unroll
    for (int mt = 0; mt < 2; ++mt) {
        float m0 = -1e30f, m1 = -1e30f;
#pragma unroll
        for (int nb = 0; nb < 8; ++nb) {
            m0 = fmaxf(m0, fmaxf(S[mt][nb][0], S[mt][nb][1]));
            m1 = fmaxf(m1, fmaxf(S[mt][nb][2], S[mt][nb][3]));
        }
        m0 = fmaxf(m0, __shfl_xor_sync(0xFFFFFFFF, m0, 1));
        m0 = fmaxf(m0, __shfl_xor_sync(0xFFFFFFFF, m0, 2));
        m1 = fmaxf(m1, __shfl_xor_sync(0xFFFFFFFF, m1, 1));
        m1 = fmaxf(m1, __shfl_xor_sync(0xFFFFFFFF, m1, 2));
        float s0 = 0.f, s1 = 0.f;
#pragma unroll
        for (int nb = 0; nb < 8; ++nb) {
            S[mt][nb][0] = __expf(S[mt][nb][0] - m0);
            S[mt][nb][1] = __expf(S[mt][nb][1] - m0);
            S[mt][nb][2] = __expf(S[mt][nb][2] - m1);
            S[mt][nb][3] = __expf(S[mt][nb][3] - m1);
            s0 += S[mt][nb][0] + S[mt][nb][1];
            s1 += S[mt][nb][2] + S[mt][nb][3];
        }
        s0 += __shfl_xor_sync(0xFFFFFFFF, s0, 1);
        s0 += __shfl_xor_sync(0xFFFFFFFF, s0, 2);
        s1 += __shfl_xor_sync(0xFFFFFFFF, s1, 1);
        s1 += __shfl_xor_sync(0xFFFFFFFF, s1, 2);
        inv[mt][0] = 1.f / s0;
        inv[mt][1] = 1.f / s1;
    }

    uint32_t pf[2][4][4];
#pragma unroll
    for (int mt = 0; mt < 2; ++mt)
#pragma unroll
        for (int kb = 0; kb < 4; ++kb) {
            pf[mt][kb][0] = h2pack(S[mt][2 * kb][0],     S[mt][2 * kb][1]);
            pf[mt][kb][1] = h2pack(S[mt][2 * kb][2],     S[mt][2 * kb][3]);
            pf[mt][kb][2] = h2pack(S[mt][2 * kb + 1][0], S[mt][2 * kb + 1][1]);
            pf[mt][kb][3] = h2pack(S[mt][2 * kb + 1][2], S[mt][2 * kb + 1][3]);
        }

    float O[2][4][4];
#pragma unroll
    for (int mt = 0; mt < 2; ++mt)
#pragma unroll
        for (int nb = 0; nb < 4; ++nb)
#pragma unroll
            for (int q = 0; q < 4; ++q) O[mt][nb][q] = 0.f;

#pragma unroll
    for (int nb = 0; nb < 4; ++nb) {
        uint32_t vf[4][2];
#pragma unroll
        for (int kb = 0; kb < 4; ++kb) {
            const __half* p = Vh + (8 * nb + g) * 72 + kb * 16 + t * 2;
            vf[kb][0] = *(const uint32_t*)p;
            vf[kb][1] = *(const uint32_t*)(p + 8);
        }
#pragma unroll
        for (int mt = 0; mt < 2; ++mt)
#pragma unroll
            for (int kb = 0; kb < 4; ++kb)
                mma16816f16(O[mt][nb], pf[mt][kb], vf[kb]);
    }

    __half* ob = g_O + (long long)w * 16384 + h * 32;
#pragma unroll
    for (int mt = 0; mt < 2; ++mt) {
        const int R = (mh * 2 + mt) * 16 + g;
#pragma unroll
        for (int nb = 0; nb < 4; ++nb) {
            const int cc = nb * 8 + t * 2;
            *reinterpret_cast<uint32_t*>(ob + R * 256 + cc) =
                h2pack(O[mt][nb][0] * inv[mt][0], O[mt][nb][1] * inv[mt][0]);
            *reinterpret_cast<uint32_t*>(ob + (R + 8) * 256 + cc) =
                h2pack(O[mt][nb][2] * inv[mt][1], O[mt][nb][3] * inv[mt][1]);
        }
    }
}

// ---------------------------------------------------------------------------
extern "C" void kernel_launch(void* const* d_in, const int* in_sizes, int n_in,
                              void* d_out, int out_size) {
    const float* xq  = (const float*)d_in[0];
    const float* xs  = (const float*)d_in[1];
    const float* Wq  = (const float*)d_in[2];
    const float* bq  = (const float*)d_in[3];
    const float* Wkv = (const float*)d_in[4];
    const float* bkv = (const float*)d_in[5];
    const float* bt  = (const float*)d_in[6];
    const float* Wp  = (const float*)d_in[7];
    const float* bp  = (const float*)d_in[8];
    float* out = (float*)d_out;

    const int M = in_sizes[0] / 256;            // 262144
    const int B = M / 64;                       // 4096
    const float scale = 0.17677669529663687f;   // 32^-0.5

    cudaFuncSetAttribute(gemm_qkv,
                         cudaFuncAttributeMaxDynamicSharedMemorySize, GSM_TOTAL);
    cudaFuncSetAttribute(gemm_out,
                         cudaFuncAttributeMaxDynamicSharedMemorySize, GSM_TOTAL);
    cudaFuncSetAttribute(attn_mma,
                         cudaFuncAttributeMaxDynamicSharedMemorySize, ASM_TOTAL);

    bias_kernel<<<128, 256>>>(bt);
    convw_all<<<1024, 256>>>(Wq, Wkv, Wp);

    gemm_qkv<<<dim3(6, M / 128), 256, GSM_TOTAL>>>(xq, xs, bq, bkv, scale);
    attn_mma<<<dim3(B, 2), 256, ASM_TOTAL>>>();
    gemm_out<<<dim3(2, M / 128), 256, GSM_TOTAL>>>(bp, out);
}

// round 17
// speedup vs baseline: 1.0218x; 1.0218x over previous
#include <cuda_runtime.h>
#include <cuda_fp16.h>
#include <cstdint>

// ---------------------------------------------------------------------------
// WindowedCrossAttention — R17
//   GEMMs: R16 (resident-B, merged QKV, fixed out-GEMM pipeline) — unchanged.
//   Attention L1 rework: V stored raw (no transpose scatter), PV B-frags via
//   ldmatrix.x4.trans; K frags via ldmatrix.x4; bias table in fp16.
// ---------------------------------------------------------------------------

__device__ __half g_Q [4096ull * 64ull * 256ull];
__device__ __half g_KV[4096ull * 64ull * 512ull];
__device__ __half g_O [4096ull * 64ull * 256ull];
__device__ __half g_bias[8 * 64 * 64];                // [h][q][k] fp16
__device__ __half g_Wh[1024 * 256];                   // [n][k]: Wq@0, Wkv@256, Wp@768

// ---- helpers ----------------------------------------------------------------
__device__ __forceinline__ uint32_t smem_u32(const void* p) {
    uint32_t a;
    asm("{ .reg .u64 t; cvta.to.shared.u64 t, %1; cvt.u32.u64 %0, t; }" : "=r"(a) : "l"(p));
    return a;
}
__device__ __forceinline__ void mma16816f16(float* c, const uint32_t* a, const uint32_t* b) {
    asm volatile(
        "mma.sync.aligned.m16n8k16.row.col.f32.f16.f16.f32 "
        "{%0,%1,%2,%3}, {%4,%5,%6,%7}, {%8,%9}, {%0,%1,%2,%3};"
        : "+f"(c[0]), "+f"(c[1]), "+f"(c[2]), "+f"(c[3])
        : "r"(a[0]), "r"(a[1]), "r"(a[2]), "r"(a[3]), "r"(b[0]), "r"(b[1]));
}
__device__ __forceinline__ void ldm_x4(uint32_t* r, uint32_t addr) {
    asm volatile("ldmatrix.sync.aligned.m8n8.x4.shared.b16 {%0,%1,%2,%3}, [%4];"
                 : "=r"(r[0]), "=r"(r[1]), "=r"(r[2]), "=r"(r[3]) : "r"(addr));
}
__device__ __forceinline__ void ldm_x4_t(uint32_t* r, uint32_t addr) {
    asm volatile("ldmatrix.sync.aligned.m8n8.x4.trans.shared.b16 {%0,%1,%2,%3}, [%4];"
                 : "=r"(r[0]), "=r"(r[1]), "=r"(r[2]), "=r"(r[3]) : "r"(addr));
}
__device__ __forceinline__ uint32_t h2pack(float a, float b) {
    __half2 h = __floats2half2_rn(a, b);
    return *reinterpret_cast<uint32_t*>(&h);
}
__device__ __forceinline__ float2 h2unpack(uint32_t u) {
    __half2 h = *reinterpret_cast<__half2*>(&u);
    return __half22float2(h);
}
#define CP_ASYNC16(dst, src) \
    asm volatile("cp.async.cg.shared.global [%0], [%1], 16;" :: "r"(dst), "l"(src))
#define CP_COMMIT() asm volatile("cp.async.commit_group;")
#define CP_WAIT0()  asm volatile("cp.async.wait_group 0;")
#define CP_WAIT1()  asm volatile("cp.async.wait_group 1;")

// ---- relative-position bias: g_bias[h][q][k] = fp16(bt[rel(q,k)][h]) ---------
__global__ void bias_kernel(const float* __restrict__ bt) {
    int idx = blockIdx.x * 256 + threadIdx.x;
    if (idx >= 8 * 64 * 64) return;
    int h  = idx >> 12;
    int nm = idx & 4095;
    int q = nm >> 6, k = nm & 63;
    int dy = (q >> 3) - (k >> 3);
    int dx = (q & 7) - (k & 7);
    int r  = (dy + 7) * 15 + (dx + 7);
    g_bias[idx] = __float2half_rn(bt[r * 8 + h]);
}

// ---- fused W transpose: Wq/Wkv/Wp -> g_Wh[1024][256] fp16 --------------------
__global__ void convw_all(const float* __restrict__ Wq,
                          const float* __restrict__ Wkv,
                          const float* __restrict__ Wp) {
    int idx = blockIdx.x * 256 + threadIdx.x;
    if (idx >= 1024 * 256) return;
    int n = idx >> 8;
    int k = idx & 255;
    float v;
    if (n < 256)       v = Wq [k * 256 + n];
    else if (n < 768)  v = Wkv[k * 512 + (n - 256)];
    else               v = Wp [k * 256 + (n - 768)];
    g_Wh[idx] = __float2half_rn(v);
}

// ---- shared GEMM machinery (R16) ----------------------------------------------
#define SM_B     1024
#define SM_A     68608
#define GSM_TOTAL (68608 + 2 * 18432)

struct GemmCtx {
    uint32_t sb, aOff, bOff;
    int wm, wn, g, tig, tid;
};

__device__ __forceinline__ void gemm_init(GemmCtx& c, uint32_t sb) {
    c.sb = sb;
    c.tid = threadIdx.x;
    int wid = c.tid >> 5, lane = c.tid & 31;
    c.g = lane >> 2; c.tig = lane & 3;
    c.wm = wid & 1; c.wn = wid >> 1;
    uint32_t lrow = lane & 15, lcol = (lane >> 4) * 8;
    c.aOff = SM_A + (c.wm * 64 + lrow) * 144 + lcol * 2;
    c.bOff = SM_B + (c.wn * 32 + lrow) * 528 + lcol * 2;
}

__device__ __forceinline__ void gemm_loadB(const GemmCtx& c, int woff, int n0) {
#pragma unroll
    for (int i = 0; i < 16; ++i) {
        int idx = c.tid + i * 256;
        int row = idx >> 5, seg = idx & 31;
        const __half* src = g_Wh + (long long)(woff + n0 + row) * 256 + seg * 8;
        CP_ASYNC16(c.sb + SM_B + row * 528 + seg * 16, src);
    }
}

__device__ __forceinline__ void gemm_mma(const GemmCtx& c, int buf, int kc,
                                         float acc[4][4][4]) {
    const uint32_t abase = c.sb + c.aOff + buf * 18432;
    const uint32_t bbase = c.sb + c.bOff + kc * 128;
#pragma unroll
    for (int ks = 0; ks < 4; ++ks) {
        uint32_t af[4][4], bm[2][4];
#pragma unroll
        for (int mf = 0; mf < 4; ++mf)
            ldm_x4(af[mf], abase + mf * 16 * 144 + ks * 32);
#pragma unroll
        for (int p = 0; p < 2; ++p)
            ldm_x4(bm[p], bbase + p * 16 * 528 + ks * 32);
#pragma unroll
        for (int mf = 0; mf < 4; ++mf)
#pragma unroll
            for (int p = 0; p < 2; ++p) {
                uint32_t b0[2] = {bm[p][0], bm[p][2]};
                uint32_t b1[2] = {bm[p][1], bm[p][3]};
                mma16816f16(acc[mf][2 * p + 0], af[mf], b0);
                mma16816f16(acc[mf][2 * p + 1], af[mf], b1);
            }
    }
}

// ---- merged Q + KV GEMM --------------------------------------------------------
__global__ __launch_bounds__(256, 2)
void gemm_qkv(const float* __restrict__ xq, const float* __restrict__ xs,
              const float* __restrict__ bq, const float* __restrict__ bkv,
              float qscale) {
    extern __shared__ __align__(1024) char smem[];
    const uint32_t sb = smem_u32(smem);
    GemmCtx c; gemm_init(c, sb);
    const int tid = c.tid;

    const bool isQ = (blockIdx.x < 2);
    const float* A     = isQ ? xq : xs;
    const float* bias  = isQ ? bq : bkv;
    const float scale  = isQ ? qscale : 1.f;
    const int   N      = isQ ? 256 : 512;
    const int   woff   = isQ ? 0 : 256;
    const int   n0     = (isQ ? blockIdx.x : blockIdx.x - 2) * 128;
    __half* C          = isQ ? g_Q : g_KV;
    const long long m0 = (long long)blockIdx.y * 128;

    float* sBias = (float*)smem;
    if (tid < 128) sBias[tid] = bias[n0 + tid];

    float acc[4][4][4];
#pragma unroll
    for (int i = 0; i < 4; ++i)
#pragma unroll
        for (int j = 0; j < 4; ++j)
#pragma unroll
            for (int q = 0; q < 4; ++q) acc[i][j][q] = 0.f;

    auto loadA = [&](int kc, float4* r) {
#pragma unroll
        for (int i = 0; i < 8; ++i) {
            int idx = tid + i * 256;
            int row = idx >> 4, q = idx & 15;
            r[i] = *reinterpret_cast<const float4*>(
                A + (m0 + row) * 256 + kc * 64 + q * 4);
        }
    };
    auto stsA = [&](int buf, const float4* r) {
        char* base = smem + SM_A + buf * 18432;
#pragma unroll
        for (int i = 0; i < 8; ++i) {
            int idx = tid + i * 256;
            int row = idx >> 4, q = idx & 15;
            float4 v = r[i];
            __half2 p0 = __floats2half2_rn(v.x, v.y);
            __half2 p1 = __floats2half2_rn(v.z, v.w);
            *reinterpret_cast<uint2*>(base + row * 144 + q * 8) =
                make_uint2(*reinterpret_cast<uint32_t*>(&p0),
                           *reinterpret_cast<uint32_t*>(&p1));
        }
    };

    gemm_loadB(c, woff, n0);
    CP_COMMIT();
    {
        float4 r[8];
        loadA(0, r);
        stsA(0, r);
    }
    CP_WAIT0();

#pragma unroll 1
    for (int kc = 0; kc < 4; ++kc) {
        float4 r[8];
        if (kc < 3) loadA(kc + 1, r);
        __syncthreads();
        if (kc < 3) stsA((kc + 1) & 1, r);
        gemm_mma(c, kc & 1, kc, acc);
    }

#pragma unroll
    for (int mf = 0; mf < 4; ++mf) {
#pragma unroll
        for (int nf = 0; nf < 4; ++nf) {
            const int cn = c.wn * 32 + nf * 8 + c.tig * 2;
            const float b0 = sBias[cn], b1 = sBias[cn + 1];
            const long long r0 = m0 + c.wm * 64 + mf * 16 + c.g;
            float v0 = scale * (acc[mf][nf][0] + b0);
            float v1 = scale * (acc[mf][nf][1] + b1);
            float v2 = scale * (acc[mf][nf][2] + b0);
            float v3 = scale * (acc[mf][nf][3] + b1);
            *reinterpret_cast<uint32_t*>(C + r0 * N + n0 + cn) = h2pack(v0, v1);
            *reinterpret_cast<uint32_t*>(C + (r0 + 8) * N + n0 + cn) = h2pack(v2, v3);
        }
    }
}

// ---- out-projection GEMM -------------------------------------------------------
__global__ __launch_bounds__(256, 2)
void gemm_out(const float* __restrict__ bias, float* __restrict__ Cp) {
    extern __shared__ __align__(1024) char smem[];
    const uint32_t sb = smem_u32(smem);
    GemmCtx c; gemm_init(c, sb);
    const int tid = c.tid;

    const int n0 = blockIdx.x * 128;
    const long long m0 = (long long)blockIdx.y * 128;

    float* sBias = (float*)smem;
    if (tid < 128) sBias[tid] = bias[n0 + tid];

    float acc[4][4][4];
#pragma unroll
    for (int i = 0; i < 4; ++i)
#pragma unroll
        for (int j = 0; j < 4; ++j)
#pragma unroll
            for (int q = 0; q < 4; ++q) acc[i][j][q] = 0.f;

    auto cpA = [&](int kc, int buf) {
        uint32_t base = sb + SM_A + buf * 18432;
#pragma unroll
        for (int i = 0; i < 4; ++i) {
            int idx = tid + i * 256;
            int row = idx >> 3, seg = idx & 7;
            const __half* src = g_O + (m0 + row) * 256 + kc * 64 + seg * 8;
            CP_ASYNC16(base + row * 144 + seg * 16, src);
        }
    };

    gemm_loadB(c, 768, n0);
    CP_COMMIT();
    cpA(0, 0);
    CP_COMMIT();

#pragma unroll 1
    for (int kc = 0; kc < 4; ++kc) {
        if (kc < 3) {
            cpA(kc + 1, (kc + 1) & 1);
            CP_COMMIT();
        }
        if (kc < 3) CP_WAIT1(); else CP_WAIT0();
        __syncthreads();
        gemm_mma(c, kc & 1, kc, acc);
        if (kc < 3) __syncthreads();
    }

#pragma unroll
    for (int mf = 0; mf < 4; ++mf) {
#pragma unroll
        for (int nf = 0; nf < 4; ++nf) {
            const int cn = c.wn * 32 + nf * 8 + c.tig * 2;
            const float b0 = sBias[cn], b1 = sBias[cn + 1];
            const long long r0 = m0 + c.wm * 64 + mf * 16 + c.g;
            float* p0 = Cp + r0 * 256 + n0 + cn;
            float* p1 = Cp + (r0 + 8) * 256 + n0 + cn;
            *reinterpret_cast<float2*>(p0) =
                make_float2(acc[mf][nf][0] + b0, acc[mf][nf][1] + b1);
            *reinterpret_cast<float2*>(p1) =
                make_float2(acc[mf][nf][2] + b0, acc[mf][nf][3] + b1);
        }
    }
}

// ---- attention: fp16 HMMA, ldmatrix datapath -----------------------------------
// block = 4 heads of 1 window, grid (B, 2), 256 threads.
// smem: sK [4][64][40] halves @0 (20480 B), sV same @20480. No V transpose.
#define ASM_TOTAL (2 * 20480)

__global__ __launch_bounds__(256, 2)
void attn_mma() {
    extern __shared__ __align__(16) char smem[];
    __half* sKp = (__half*)smem;
    const uint32_t sb = smem_u32(smem);

    const int w  = blockIdx.x;
    const int hg = blockIdx.y;
    const int tid = threadIdx.x;
    const __half* kvb = g_KV + (long long)w * 32768 + hg * 128;

    // stage K and V: raw uint4 copies, identical [key][40] layout
#pragma unroll
    for (int i = 0; i < 4; ++i) {
        int idx = tid + i * 256;                 // 0..1023
        int hl  = idx >> 8;
        int rem = idx & 255;
        int key = rem >> 2;
        int d8  = (rem & 3) * 8;
        const __half* src = kvb + key * 512 + hl * 32 + d8;
        __half* dst = sKp + hl * 2560 + key * 40 + d8;
        *reinterpret_cast<uint4*>(dst) = *reinterpret_cast<const uint4*>(src);
        *reinterpret_cast<uint4*>(dst + 10240) =
            *reinterpret_cast<const uint4*>(src + 256);   // sV at +20480 B
    }
    __syncthreads();

    const int wid = tid >> 5, lane = tid & 31;
    const int g = lane >> 2, t = lane & 3;
    const int hl = wid >> 1, mh = wid & 1;
    const int h  = hg * 4 + hl;

    // per-lane ldmatrix base addresses (row = lane&15, col-half = lane>>4)
    const uint32_t lmOff = (uint32_t)(lane & 15) * 80 + (uint32_t)(lane >> 4) * 16;
    const uint32_t Kb = sb + hl * 5120 + lmOff;
    const uint32_t Vb = sb + 20480 + hl * 5120 + lmOff;

    // Q fragments: LDG.32 of fp16 pairs
    uint32_t qf[2][2][4];
    const __half* qbase = g_Q + (long long)w * 16384 + h * 32;
#pragma unroll
    for (int mt = 0; mt < 2; ++mt) {
        const int R = (mh * 2 + mt) * 16 + g;
#pragma unroll
        for (int kb = 0; kb < 2; ++kb) {
            const int cc = kb * 16 + t * 2;
            qf[mt][kb][0] = *reinterpret_cast<const uint32_t*>(qbase + R * 256 + cc);
            qf[mt][kb][1] = *reinterpret_cast<const uint32_t*>(qbase + (R + 8) * 256 + cc);
            qf[mt][kb][2] = *reinterpret_cast<const uint32_t*>(qbase + R * 256 + cc + 8);
            qf[mt][kb][3] = *reinterpret_cast<const uint32_t*>(qbase + (R + 8) * 256 + cc + 8);
        }
    }

    // ---- S = Q K^T : K B-frags via ldmatrix.x4 ----
    float S[2][8][4];
#pragma unroll
    for (int mt = 0; mt < 2; ++mt)
#pragma unroll
        for (int nb = 0; nb < 8; ++nb)
#pragma unroll
            for (int q = 0; q < 4; ++q) S[mt][nb][q] = 0.f;

#pragma unroll
    for (int nbp = 0; nbp < 4; ++nbp) {           // key blocks of 16
#pragma unroll
        for (int kb = 0; kb < 2; ++kb) {          // d halves of 16
            uint32_t bm[4];
            ldm_x4(bm, Kb + nbp * 16 * 80 + kb * 32);
            uint32_t b0[2] = {bm[0], bm[2]};      // keys 8nbp*2..+7
            uint32_t b1[2] = {bm[1], bm[3]};      // keys +8..15
#pragma unroll
            for (int mt = 0; mt < 2; ++mt) {
                mma16816f16(S[mt][2 * nbp + 0], qf[mt][kb], b0);
                mma16816f16(S[mt][2 * nbp + 1], qf[mt][kb], b1);
            }
        }
    }

    // ---- + bias (fp16 table, uint32 loads) ----
    const __half* bb = g_bias + h * 4096;
#pragma unroll
    for (int mt = 0; mt < 2; ++mt) {
        const int R = (mh * 2 + mt) * 16 + g;
#pragma unroll
        for (int nb = 0; nb < 8; ++nb) {
            const int cc = nb * 8 + t * 2;
            float2 b0 = h2unpack(*reinterpret_cast<const uint32_t*>(bb + R * 64 + cc));
            float2 b1 = h2unpack(*reinterpret_cast<const uint32_t*>(bb + (R + 8) * 64 + cc));
            S[mt][nb][0] += b0.x; S[mt][nb][1] += b0.y;
            S[mt][nb][2] += b1.x; S[mt][nb][3] += b1.y;
        }
    }

    // ---- row softmax ----
    float inv[2][2];
#pragma unroll
    for (int mt = 0; mt < 2; ++mt) {
        float m0 = -1e30f, m1 = -1e30f;
#pragma unroll
        for (int nb = 0; nb < 8; ++nb) {
            m0 = fmaxf(m0, fmaxf(S[mt][nb][0], S[mt][nb][1]));
            m1 = fmaxf(m1, fmaxf(S[mt][nb][2], S[mt][nb][3]));
        }
        m0 = fmaxf(m0, __shfl_xor_sync(0xFFFFFFFF, m0, 1));
        m0 = fmaxf(m0, __shfl_xor_sync(0xFFFFFFFF, m0, 2));
        m1 = fmaxf(m1, __shfl_xor_sync(0xFFFFFFFF, m1, 1));
        m1 = fmaxf(m1, __shfl_xor_sync(0xFFFFFFFF, m1, 2));
        float s0 = 0.f, s1 = 0.f;
#pragma unroll
        for (int nb = 0; nb < 8; ++nb) {
            S[mt][nb][0] = __expf(S[mt][nb][0] - m0);
            S[mt][nb][1] = __expf(S[mt][nb][1] - m0);
            S[mt][nb][2] = __expf(S[mt][nb][2] - m1);
            S[mt][nb][3] = __expf(S[mt][nb][3] - m1);
            s0 += S[mt][nb][0] + S[mt][nb][1];
            s1 += S[mt][nb][2] + S[mt][nb][3];
        }
        s0 += __shfl_xor_sync(0xFFFFFFFF, s0, 1);
        s0 += __shfl_xor_sync(0xFFFFFFFF, s0, 2);
        s1 += __shfl_xor_sync(0xFFFFFFFF, s1, 1);
        s1 += __shfl_xor_sync(0xFFFFFFFF, s1, 2);
        inv[mt][0] = 1.f / s0;
        inv[mt][1] = 1.f / s1;
    }

    // ---- repack P (unnormalized) into A-fragments ----
    uint32_t pf[2][4][4];
#pragma unroll
    for (int mt = 0; mt < 2; ++mt)
#pragma unroll
        for (int kb = 0; kb < 4; ++kb) {
            pf[mt][kb][0] = h2pack(S[mt][2 * kb][0],     S[mt][2 * kb][1]);
            pf[mt][kb][1] = h2pack(S[mt][2 * kb][2],     S[mt][2 * kb][3]);
            pf[mt][kb][2] = h2pack(S[mt][2 * kb + 1][0], S[mt][2 * kb + 1][1]);
            pf[mt][kb][3] = h2pack(S[mt][2 * kb + 1][2], S[mt][2 * kb + 1][3]);
        }

    // ---- O = P V : V B-frags via ldmatrix.x4.trans on raw [key][d] ----
    float O[2][4][4];
#pragma unroll
    for (int mt = 0; mt < 2; ++mt)
#pragma unroll
        for (int nb = 0; nb < 4; ++nb)
#pragma unroll
            for (int q = 0; q < 4; ++q) O[mt][nb][q] = 0.f;

#pragma unroll
    for (int kb = 0; kb < 4; ++kb) {              // key blocks of 16
#pragma unroll
        for (int dp = 0; dp < 2; ++dp) {          // d pairs (nb 2dp, 2dp+1)
            uint32_t vm[4];
            ldm_x4_t(vm, Vb + kb * 16 * 80 + dp * 32);
            // vm0 = b0(nb=2dp), vm1 = b1(nb=2dp), vm2/vm3 for nb=2dp+1
            uint32_t v0[2] = {vm[0], vm[1]};
            uint32_t v1[2] = {vm[2], vm[3]};
#pragma unroll
            for (int mt = 0; mt < 2; ++mt) {
                mma16816f16(O[mt][2 * dp + 0], pf[mt][kb], v0);
                mma16816f16(O[mt][2 * dp + 1], pf[mt][kb], v1);
            }
        }
    }

    // ---- normalize + store fp16 ----
    __half* ob = g_O + (long long)w * 16384 + h * 32;
#pragma unroll
    for (int mt = 0; mt < 2; ++mt) {
        const int R = (mh * 2 + mt) * 16 + g;
#pragma unroll
        for (int nb = 0; nb < 4; ++nb) {
            const int cc = nb * 8 + t * 2;
            *reinterpret_cast<uint32_t*>(ob + R * 256 + cc) =
                h2pack(O[mt][nb][0] * inv[mt][0], O[mt][nb][1] * inv[mt][0]);
            *reinterpret_cast<uint32_t*>(ob + (R + 8) * 256 + cc) =
                h2pack(O[mt][nb][2] * inv[mt][1], O[mt][nb][3] * inv[mt][1]);
        }
    }
}

// ---------------------------------------------------------------------------
extern "C" void kernel_launch(void* const* d_in, const int* in_sizes, int n_in,
                              void* d_out, int out_size) {
    const float* xq  = (const float*)d_in[0];
    const float* xs  = (const float*)d_in[1];
    const float* Wq  = (const float*)d_in[2];
    const float* bq  = (const float*)d_in[3];
    const float* Wkv = (const float*)d_in[4];
    const float* bkv = (const float*)d_in[5];
    const float* bt  = (const float*)d_in[6];
    const float* Wp  = (const float*)d_in[7];
    const float* bp  = (const float*)d_in[8];
    float* out = (float*)d_out;

    const int M = in_sizes[0] / 256;            // 262144
    const int B = M / 64;                       // 4096
    const float scale = 0.17677669529663687f;   // 32^-0.5

    cudaFuncSetAttribute(gemm_qkv,
                         cudaFuncAttributeMaxDynamicSharedMemorySize, GSM_TOTAL);
    cudaFuncSetAttribute(gemm_out,
                         cudaFuncAttributeMaxDynamicSharedMemorySize, GSM_TOTAL);
    cudaFuncSetAttribute(attn_mma,
                         cudaFuncAttributeMaxDynamicSharedMemorySize, ASM_TOTAL);

    bias_kernel<<<128, 256>>>(bt);
    convw_all<<<1024, 256>>>(Wq, Wkv, Wp);

    gemm_qkv<<<dim3(6, M / 128), 256, GSM_TOTAL>>>(xq, xs, bq, bkv, scale);
    attn_mma<<<dim3(B, 2), 256, ASM_TOTAL>>>();
    gemm_out<<<dim3(2, M / 128), 256, GSM_TOTAL>>>(bp, out);
}